// round 4
// baseline (speedup 1.0000x reference)
#include <cuda_runtime.h>
#include <cuda_fp16.h>
#include <cstdint>

#define T_  512
#define B_  128
#define I_  512
#define H_  1024
#define NG  4096   // 4 * H
#define KZ  1536   // H + I
#define GRID_STEP 128

// ---------------- device scratch (static: no allocation allowed) -------------
__device__ __half g_xh[(size_t)T_ * B_ * I_];     //  64 MB  x in fp16
__device__ __half g_gx[(size_t)T_ * B_ * NG];     // 512 MB  precomputed x-part of gates (+bias), fp16
__device__ __half g_Wh[(size_t)NG * H_];          //   8 MB  recurrent weights fp16, n = g*H + j
__device__ __half g_Wx[(size_t)NG * I_];          //   4 MB  input weights fp16
__device__ __half g_h[2][B_ * H_];                // ping-pong hidden state (fp16)
__device__ int    g_flag[T_];                     // per-step completion counters

// ---------------- helpers ----------------------------------------------------
__device__ __forceinline__ float sigm(float x) {
    return 1.0f / (1.0f + __expf(-x));
}
__device__ __forceinline__ float tanh_fast(float x) {
    float e = __expf(-2.0f * fabsf(x));
    float r = (1.0f - e) / (1.0f + e);
    return copysignf(r, x);
}
__device__ __forceinline__ void mma16816(float* d, const uint32_t* a, uint32_t b0, uint32_t b1) {
    asm volatile(
        "mma.sync.aligned.m16n8k16.row.col.f32.f16.f16.f32 "
        "{%0,%1,%2,%3}, {%4,%5,%6,%7}, {%8,%9}, {%0,%1,%2,%3};\n"
        : "+f"(d[0]), "+f"(d[1]), "+f"(d[2]), "+f"(d[3])
        : "r"(a[0]), "r"(a[1]), "r"(a[2]), "r"(a[3]),
          "r"(b0), "r"(b1));
}
__device__ __forceinline__ void cp_async16(uint32_t smem_addr, const void* gptr) {
    asm volatile("cp.async.cg.shared.global [%0], [%1], 16;\n" :: "r"(smem_addr), "l"(gptr));
}
__device__ __forceinline__ int ld_acquire_gpu(const int* p) {
    int v;
    asm volatile("ld.acquire.gpu.b32 %0, [%1];\n" : "=r"(v) : "l"(p) : "memory");
    return v;
}

// ---------------- prep kernels ------------------------------------------------
__global__ void k_prep_weights(const float* __restrict__ Wf, const float* __restrict__ Wi,
                               const float* __restrict__ Wc, const float* __restrict__ Wo) {
    size_t idx = (size_t)blockIdx.x * blockDim.x + threadIdx.x;
    const size_t total = (size_t)NG * KZ;
    if (idx < total) {
        int n = (int)(idx / KZ);
        int k = (int)(idx % KZ);
        int g = n >> 10, j = n & 1023;
        const float* W = (g == 0) ? Wf : (g == 1) ? Wi : (g == 2) ? Wc : Wo;
        float v = W[(size_t)j * KZ + k];
        if (k < H_) g_Wh[(size_t)n * H_ + k]        = __float2half(v);
        else        g_Wx[(size_t)n * I_ + (k - H_)] = __float2half(v);
    }
    if (idx < (size_t)B_ * H_) g_h[0][idx] = __float2half(0.0f);
    if (idx < T_) g_flag[idx] = 0;
}

__global__ void k_convert_x(const float* __restrict__ x) {
    size_t idx = (size_t)blockIdx.x * blockDim.x + threadIdx.x;
    if (idx < (size_t)T_ * B_ * I_) g_xh[idx] = __float2half(x[idx]);
}

// ---------------- kernel A: gx = x @ Wx^T + b  (M=65536, N=4096, K=512) -------
__global__ __launch_bounds__(256) void k_gx(const float* __restrict__ bf, const float* __restrict__ bi,
                                            const float* __restrict__ bc, const float* __restrict__ bo) {
    __shared__ __half As[128][40];
    __shared__ __half Bs[128][40];

    const int m0 = blockIdx.y * 128;
    const int n0 = blockIdx.x * 128;
    const int tid  = threadIdx.x;
    const int w    = tid >> 5;
    const int lane = tid & 31;
    const int gid  = lane >> 2;
    const int t4   = lane & 3;
    const int wm   = w >> 1;
    const int wn   = w & 1;

    float acc[2][8][4];
#pragma unroll
    for (int mt = 0; mt < 2; mt++)
#pragma unroll
        for (int nt = 0; nt < 8; nt++)
#pragma unroll
            for (int e = 0; e < 4; e++) acc[mt][nt][e] = 0.0f;

    for (int kb = 0; kb < I_; kb += 32) {
#pragma unroll
        for (int i = 0; i < 2; i++) {
            int cid = tid + i * 256;
            int r = cid >> 2, ch = cid & 3;
            *(uint4*)&As[r][ch * 8] = *(const uint4*)&g_xh[(size_t)(m0 + r) * I_ + kb + ch * 8];
            *(uint4*)&Bs[r][ch * 8] = *(const uint4*)&g_Wx[(size_t)(n0 + r) * I_ + kb + ch * 8];
        }
        __syncthreads();

#pragma unroll
        for (int ks = 0; ks < 2; ks++) {
            const int ko = ks * 16;
            uint32_t a[2][4], b[8][2];
#pragma unroll
            for (int mt = 0; mt < 2; mt++) {
                int r = wm * 32 + mt * 16 + gid;
                a[mt][0] = *(const uint32_t*)&As[r][ko + t4 * 2];
                a[mt][1] = *(const uint32_t*)&As[r + 8][ko + t4 * 2];
                a[mt][2] = *(const uint32_t*)&As[r][ko + t4 * 2 + 8];
                a[mt][3] = *(const uint32_t*)&As[r + 8][ko + t4 * 2 + 8];
            }
#pragma unroll
            for (int nt = 0; nt < 8; nt++) {
                int c = wn * 64 + nt * 8 + gid;
                b[nt][0] = *(const uint32_t*)&Bs[c][ko + t4 * 2];
                b[nt][1] = *(const uint32_t*)&Bs[c][ko + t4 * 2 + 8];
            }
#pragma unroll
            for (int mt = 0; mt < 2; mt++)
#pragma unroll
                for (int nt = 0; nt < 8; nt++)
                    mma16816(acc[mt][nt], a[mt], b[nt][0], b[nt][1]);
        }
        __syncthreads();
    }

#pragma unroll
    for (int nt = 0; nt < 8; nt++) {
        int n = n0 + wn * 64 + nt * 8 + t4 * 2;
        int g = n >> 10, j = n & 1023;
        const float* bias = (g == 0) ? bf : (g == 1) ? bi : (g == 2) ? bc : bo;
        float b0 = bias[j], b1 = bias[j + 1];
#pragma unroll
        for (int mt = 0; mt < 2; mt++) {
            int m = m0 + wm * 32 + mt * 16 + gid;
            __half2 v0 = __floats2half2_rn(acc[mt][nt][0] + b0, acc[mt][nt][1] + b1);
            __half2 v1 = __floats2half2_rn(acc[mt][nt][2] + b0, acc[mt][nt][3] + b1);
            *(__half2*)&g_gx[(size_t)m * NG + n]       = v0;
            *(__half2*)&g_gx[(size_t)(m + 8) * NG + n] = v1;
        }
    }
}

// ---------------- kernel B: persistent LSTM scan -------------------------------
// 128 blocks: block (mhalf, jb) owns rows [mhalf*64, +64) x cols j0=jb*16 (+16) x 4 gates.
// Wh slice (4 x 16 x 1024 fp16 = 128KB) resident in SMEM for all 512 steps.
// Per step: stream h (64 x 1024 fp16) via cp.async.cg (L2-coherent) in 8 double-
// buffered 16KB chunks; HMMA; fused gate epilogue; flag-based global sync.
#define WS_LD 1032          // 1024 + 8 halfs pad
#define HS_LD 136           // 128 + 8 halfs pad
#define SMEM_STEP_BYTES ((64 * WS_LD + 2 * 64 * HS_LD) * 2)

__global__ __launch_bounds__(256, 1) void k_scan(float* __restrict__ out) {
    extern __shared__ __half smem[];
    __half* ws = smem;                      // [64][WS_LD]  row = g*16 + jl
    __half* hs = smem + 64 * WS_LD;         // [2][64][HS_LD]

    const int tid  = threadIdx.x;
    const int w    = tid >> 5;
    const int lane = tid & 31;
    const int gid  = lane >> 2;
    const int t4   = lane & 3;
    const int wm   = w >> 1;                // 0..3  (m-tile)
    const int wn   = w & 1;                 // 0..1  (j-subrange)

    const int mhalf = blockIdx.x & 1;
    const int jb    = blockIdx.x >> 1;
    const int j0    = jb * 16;

    // ---- load Wh slice once: 64 rows x 1024 halfs = 8192 x 16B chunks ----
    for (int i = 0; i < 32; i++) {
        int cid = tid + i * 256;            // 0..8191 (16B chunks)
        int r = cid >> 7, ch = cid & 127;   // row 0..63, chunk 0..127
        int g = r >> 4, jl = r & 15;
        *(uint4*)&ws[r * WS_LD + ch * 8] =
            *(const uint4*)&g_Wh[(size_t)(g * H_ + j0 + jl) * H_ + ch * 8];
    }
    __syncthreads();

    const uint32_t hs_base = (uint32_t)__cvta_generic_to_shared(hs);

    // persistent per-thread cell state: rows (gid, gid+8), cols (t4*2, t4*2+1)
    float cst[4] = {0.f, 0.f, 0.f, 0.f};

    const int my_r   = wm * 16 + gid;                   // local row in 64-row half
    const int my_j   = j0 + wn * 8 + t4 * 2;            // global j (even)
    const int wrow   = wn * 8 + gid;                    // ws row within gate block

    for (int t = 0; t < T_; t++) {
        const __half* __restrict__ hin = g_h[t & 1];
        __half* __restrict__ hout      = g_h[(t + 1) & 1];

        if (t > 0) {
            if (tid == 0) {
                while (ld_acquire_gpu(&g_flag[t - 1]) != GRID_STEP) {}
            }
            __syncthreads();
        }

        const __half* hsrc = hin + (size_t)(mhalf * 64) * H_;

        // preload chunk 0
        {
#pragma unroll
            for (int i = 0; i < 4; i++) {
                int cid = tid + i * 256;        // 0..1023
                int r = cid >> 4, ch = cid & 15;
                cp_async16(hs_base + (uint32_t)((r * HS_LD + ch * 8) * 2),
                           hsrc + (size_t)r * H_ + ch * 8);
            }
            asm volatile("cp.async.commit_group;\n");
        }

        float acc[4][4];
#pragma unroll
        for (int g = 0; g < 4; g++)
#pragma unroll
            for (int e = 0; e < 4; e++) acc[g][e] = 0.f;

#pragma unroll 1
        for (int c8 = 0; c8 < 8; c8++) {
            if (c8 < 7) {
                int nb = (c8 + 1) & 1;
#pragma unroll
                for (int i = 0; i < 4; i++) {
                    int cid = tid + i * 256;
                    int r = cid >> 4, ch = cid & 15;
                    cp_async16(hs_base + (uint32_t)(((nb * 64 + r) * HS_LD + ch * 8) * 2),
                               hsrc + (size_t)r * H_ + (c8 + 1) * 128 + ch * 8);
                }
                asm volatile("cp.async.commit_group;\n");
                asm volatile("cp.async.wait_group 1;\n");
            } else {
                asm volatile("cp.async.wait_group 0;\n");
            }
            __syncthreads();

            const __half* hb = hs + (c8 & 1) * 64 * HS_LD;
#pragma unroll
            for (int ks = 0; ks < 8; ks++) {
                const int ko = ks * 16;
                uint32_t a[4];
                a[0] = *(const uint32_t*)&hb[(my_r)     * HS_LD + ko + t4 * 2];
                a[1] = *(const uint32_t*)&hb[(my_r + 8) * HS_LD + ko + t4 * 2];
                a[2] = *(const uint32_t*)&hb[(my_r)     * HS_LD + ko + t4 * 2 + 8];
                a[3] = *(const uint32_t*)&hb[(my_r + 8) * HS_LD + ko + t4 * 2 + 8];
                const int kb = c8 * 128 + ko;
#pragma unroll
                for (int g = 0; g < 4; g++) {
                    const __half* wr = &ws[(g * 16 + wrow) * WS_LD + kb];
                    uint32_t b0 = *(const uint32_t*)&wr[t4 * 2];
                    uint32_t b1 = *(const uint32_t*)&wr[t4 * 2 + 8];
                    mma16816(acc[g], a, b0, b1);
                }
            }
            __syncthreads();
        }

        // ---- epilogue: gates + cell update + writes ----
#pragma unroll
        for (int rr = 0; rr < 2; rr++) {
            const int b_row = mhalf * 64 + my_r + rr * 8;
            const size_t gxb = ((size_t)t * B_ + b_row) * NG + my_j;
            __half2 gf = *(const __half2*)&g_gx[gxb + 0 * H_];
            __half2 gi = *(const __half2*)&g_gx[gxb + 1 * H_];
            __half2 gc = *(const __half2*)&g_gx[gxb + 2 * H_];
            __half2 go = *(const __half2*)&g_gx[gxb + 3 * H_];
            float2 ff = __half22float2(gf);
            float2 fi = __half22float2(gi);
            float2 fc = __half22float2(gc);
            float2 fo = __half22float2(go);

            float hres[2];
#pragma unroll
            for (int cc = 0; cc < 2; cc++) {
                const int ai = rr * 2 + cc;
                float pf = acc[0][ai] + (cc ? ff.y : ff.x);
                float pi = acc[1][ai] + (cc ? fi.y : fi.x);
                float pc = acc[2][ai] + (cc ? fc.y : fc.x);
                float po = acc[3][ai] + (cc ? fo.y : fo.x);
                float f  = sigm(pf);
                float ii = sigm(pi);
                float ct = tanh_fast(pc);
                float o  = sigm(po);
                float cnew = f * cst[ai] + ii * ct;
                cst[ai] = cnew;
                hres[cc] = o * tanh_fast(cnew);
            }
            *(float2*)&out[((size_t)t * B_ + b_row) * H_ + my_j] = make_float2(hres[0], hres[1]);
            *(__half2*)&hout[(size_t)b_row * H_ + my_j] = __floats2half2_rn(hres[0], hres[1]);
        }

        __threadfence();
        __syncthreads();
        if (tid == 0) atomicAdd(&g_flag[t], 1);
    }
}

// ---------------- launch ------------------------------------------------------
extern "C" void kernel_launch(void* const* d_in, const int* in_sizes, int n_in,
                              void* d_out, int out_size) {
    const float* x  = (const float*)d_in[0];
    const float* Wf = (const float*)d_in[1];
    const float* bf = (const float*)d_in[2];
    const float* Wi = (const float*)d_in[3];
    const float* bi = (const float*)d_in[4];
    const float* Wc = (const float*)d_in[5];
    const float* bc = (const float*)d_in[6];
    const float* Wo = (const float*)d_in[7];
    const float* bo = (const float*)d_in[8];
    float* out = (float*)d_out;

    cudaFuncSetAttribute(k_scan, cudaFuncAttributeMaxDynamicSharedMemorySize, SMEM_STEP_BYTES);

    {
        size_t total = (size_t)NG * KZ;
        int blocks = (int)((total + 255) / 256);
        k_prep_weights<<<blocks, 256>>>(Wf, Wi, Wc, Wo);
    }
    {
        size_t total = (size_t)T_ * B_ * I_;
        int blocks = (int)((total + 255) / 256);
        k_convert_x<<<blocks, 256>>>(x);
    }
    k_gx<<<dim3(NG / 128, (T_ * B_) / 128), 256>>>(bf, bi, bc, bo);

    k_scan<<<GRID_STEP, 256, SMEM_STEP_BYTES>>>(out);
}

// round 6
// speedup vs baseline: 1.0311x; 1.0311x over previous
#include <cuda_runtime.h>
#include <cuda_fp16.h>
#include <cstdint>

#define T_  512
#define B_  128
#define I_  512
#define H_  1024
#define NG  4096
#define KZ  1536
#define SCAN_BLOCKS  128
#define SCAN_THREADS 512

__device__ __half g_xh[(size_t)T_ * B_ * I_];
__device__ __half g_gx[(size_t)T_ * B_ * NG];
__device__ __half g_Wh[(size_t)NG * H_];
__device__ __half g_Wx[(size_t)NG * I_];
__device__ __half g_h[2][B_ * H_];
__device__ int    g_flag[T_];

__device__ __forceinline__ float sigm(float x) { return 1.0f / (1.0f + __expf(-x)); }
__device__ __forceinline__ float tanh_fast(float x) {
    float e = __expf(-2.0f * fabsf(x));
    return copysignf((1.0f - e) / (1.0f + e), x);
}
__device__ __forceinline__ void mma16816(float* d, const uint32_t* a, uint32_t b0, uint32_t b1) {
    asm volatile(
        "mma.sync.aligned.m16n8k16.row.col.f32.f16.f16.f32 "
        "{%0,%1,%2,%3}, {%4,%5,%6,%7}, {%8,%9}, {%0,%1,%2,%3};\n"
        : "+f"(d[0]), "+f"(d[1]), "+f"(d[2]), "+f"(d[3])
        : "r"(a[0]), "r"(a[1]), "r"(a[2]), "r"(a[3]), "r"(b0), "r"(b1));
}
__device__ __forceinline__ void ldsm_x4(uint32_t* r, uint32_t addr) {
    asm volatile("ldmatrix.sync.aligned.m8n8.x4.shared.b16 {%0,%1,%2,%3}, [%4];"
                 : "=r"(r[0]), "=r"(r[1]), "=r"(r[2]), "=r"(r[3]) : "r"(addr));
}
__device__ __forceinline__ void cp_async16(uint32_t s, const void* g) {
    asm volatile("cp.async.cg.shared.global [%0], [%1], 16;\n" :: "r"(s), "l"(g));
}
__device__ __forceinline__ int ld_acquire_gpu(const int* p) {
    int v; asm volatile("ld.acquire.gpu.b32 %0, [%1];\n" : "=r"(v) : "l"(p) : "memory"); return v;
}
__device__ __forceinline__ uint32_t smem_u32(const void* p) {
    uint32_t a; asm("{ .reg .u64 t; cvta.to.shared.u64 t, %1; cvt.u32.u64 %0, t; }" : "=r"(a) : "l"(p)); return a;
}

// ---------------- prep ----------------------------------------------------
__global__ void k_prep_weights(const float* __restrict__ Wf, const float* __restrict__ Wi,
                               const float* __restrict__ Wc, const float* __restrict__ Wo) {
    size_t idx = (size_t)blockIdx.x * blockDim.x + threadIdx.x;
    if (idx < (size_t)NG * KZ) {
        int n = (int)(idx / KZ), k = (int)(idx % KZ);
        int g = n >> 10, j = n & 1023;
        const float* W = (g == 0) ? Wf : (g == 1) ? Wi : (g == 2) ? Wc : Wo;
        float v = W[(size_t)j * KZ + k];
        if (k < H_) g_Wh[(size_t)n * H_ + k]        = __float2half(v);
        else        g_Wx[(size_t)n * I_ + (k - H_)] = __float2half(v);
    }
    if (idx < (size_t)B_ * H_) g_h[0][idx] = __float2half(0.0f);
    if (idx < T_) g_flag[idx] = 0;
}

__global__ void k_convert_x(const float* __restrict__ x) {
    size_t idx = (size_t)blockIdx.x * blockDim.x + threadIdx.x;
    if (idx < (size_t)T_ * B_ * I_) g_xh[idx] = __float2half(x[idx]);
}

// ---------------- gx GEMM (unchanged, passing) -----------------------------
__global__ __launch_bounds__(256) void k_gx(const float* __restrict__ bf, const float* __restrict__ bi,
                                            const float* __restrict__ bc, const float* __restrict__ bo) {
    __shared__ __half As[128][40];
    __shared__ __half Bs[128][40];
    const int m0 = blockIdx.y * 128, n0 = blockIdx.x * 128;
    const int tid = threadIdx.x, w = tid >> 5, lane = tid & 31;
    const int gid = lane >> 2, t4 = lane & 3, wm = w >> 1, wn = w & 1;

    float acc[2][8][4];
#pragma unroll
    for (int mt = 0; mt < 2; mt++)
#pragma unroll
        for (int nt = 0; nt < 8; nt++)
#pragma unroll
            for (int e = 0; e < 4; e++) acc[mt][nt][e] = 0.0f;

    for (int kb = 0; kb < I_; kb += 32) {
#pragma unroll
        for (int i = 0; i < 2; i++) {
            int cid = tid + i * 256, r = cid >> 2, ch = cid & 3;
            *(uint4*)&As[r][ch * 8] = *(const uint4*)&g_xh[(size_t)(m0 + r) * I_ + kb + ch * 8];
            *(uint4*)&Bs[r][ch * 8] = *(const uint4*)&g_Wx[(size_t)(n0 + r) * I_ + kb + ch * 8];
        }
        __syncthreads();
#pragma unroll
        for (int ks = 0; ks < 2; ks++) {
            const int ko = ks * 16;
            uint32_t a[2][4], b[8][2];
#pragma unroll
            for (int mt = 0; mt < 2; mt++) {
                int r = wm * 32 + mt * 16 + gid;
                a[mt][0] = *(const uint32_t*)&As[r][ko + t4 * 2];
                a[mt][1] = *(const uint32_t*)&As[r + 8][ko + t4 * 2];
                a[mt][2] = *(const uint32_t*)&As[r][ko + t4 * 2 + 8];
                a[mt][3] = *(const uint32_t*)&As[r + 8][ko + t4 * 2 + 8];
            }
#pragma unroll
            for (int nt = 0; nt < 8; nt++) {
                int c = wn * 64 + nt * 8 + gid;
                b[nt][0] = *(const uint32_t*)&Bs[c][ko + t4 * 2];
                b[nt][1] = *(const uint32_t*)&Bs[c][ko + t4 * 2 + 8];
            }
#pragma unroll
            for (int mt = 0; mt < 2; mt++)
#pragma unroll
                for (int nt = 0; nt < 8; nt++)
                    mma16816(acc[mt][nt], a[mt], b[nt][0], b[nt][1]);
        }
        __syncthreads();
    }
#pragma unroll
    for (int nt = 0; nt < 8; nt++) {
        int n = n0 + wn * 64 + nt * 8 + t4 * 2;
        int g = n >> 10, j = n & 1023;
        const float* bias = (g == 0) ? bf : (g == 1) ? bi : (g == 2) ? bc : bo;
        float b0 = bias[j], b1 = bias[j + 1];
#pragma unroll
        for (int mt = 0; mt < 2; mt++) {
            int m = m0 + wm * 32 + mt * 16 + gid;
            *(__half2*)&g_gx[(size_t)m * NG + n]       = __floats2half2_rn(acc[mt][nt][0] + b0, acc[mt][nt][1] + b1);
            *(__half2*)&g_gx[(size_t)(m + 8) * NG + n] = __floats2half2_rn(acc[mt][nt][2] + b0, acc[mt][nt][3] + b1);
        }
    }
}

// ---------------- persistent LSTM scan (HMMA + ldmatrix + k-split) ----------
// 128 blocks x 512 thr (16 warps). Block (mhalf,jb): rows mhalf*64(+64) x 16 j x 4 gates.
// Warp w: kg=w>>3 (k-half), wm=(w>>3==..)&: ww=w&7, wm=ww>>1 (m-tile), wn=ww&1 (j-half).
// Wh 64x1024 fp16 in SMEM for all steps. h streamed as 4 pair-chunks (2x16KB),
// kg0 computes even chunks, kg1 odd; 20-float-strided SMEM reduce merges halves.
#define HS_LD 136
#define CHK   (64 * HS_LD)
#define WS_LD 1032
#define WS_HALFS (64 * WS_LD)
#define SCAN_SMEM ((WS_HALFS + 4 * CHK) * 2)

__global__ __launch_bounds__(SCAN_THREADS, 1) void k_scan(float* __restrict__ out) {
    extern __shared__ __half sm[];
    __half* ws = sm;                 // [64][WS_LD], row = g*16 + jl
    __half* hs = sm + WS_HALFS;      // 4 buffers [64][HS_LD]

    const int tid  = threadIdx.x;
    const int w    = tid >> 5;
    const int lane = tid & 31;
    const int kg   = w >> 3;         // 0/1: even/odd k-chunks
    const int ww   = w & 7;
    const int wm   = ww >> 1;        // 0..3
    const int wn   = ww & 1;         // 0..1
    const int gid  = lane >> 2;
    const int t4   = lane & 3;

    const int mhalf = blockIdx.x & 1;
    const int jb    = blockIdx.x >> 1;
    const int j0    = jb * 16;

    // ---- Wh slice once: 64 rows x 1024 halfs = 8192 16B chunks ----
#pragma unroll 4
    for (int i = 0; i < 16; i++) {
        int cid = tid + i * SCAN_THREADS;
        int r = cid >> 7, ch = cid & 127;
        int g = r >> 4, jl = r & 15;
        *(uint4*)&ws[r * WS_LD + ch * 8] =
            *(const uint4*)&g_Wh[(size_t)(g * H_ + j0 + jl) * H_ + ch * 8];
    }
    __syncthreads();

    const uint32_t hs_base = smem_u32(hs);
    const uint32_t ws_base = smem_u32(ws);

    // ldmatrix lane addresses (bytes)
    const int a_row  = wm * 16 + ((lane >> 3) & 1) * 8 + (lane & 7);
    const int a_col8 = (lane >> 4) * 8;
    const uint32_t a_lane_off = (uint32_t)((a_row * HS_LD + a_col8) * 2);
    // B: gate pair base (gates gb, gb+1): row = (gb + (lane>>4))*16 + wn*8 + (lane&7)
    const uint32_t b_lane0 = ws_base + (uint32_t)(((((lane >> 4) + 0) * 16 + wn * 8 + (lane & 7)) * WS_LD
                                                   + ((lane >> 3) & 1) * 8) * 2);
    const uint32_t b_lane1 = ws_base + (uint32_t)(((((lane >> 4) + 2) * 16 + wn * 8 + (lane & 7)) * WS_LD
                                                   + ((lane >> 3) & 1) * 8) * 2);

    const int my_r = wm * 16 + gid;
    const int my_j = j0 + wn * 8 + t4 * 2;

    float cst[4] = {0.f, 0.f, 0.f, 0.f};    // kg0 warps only

    for (int t = 0; t < T_; t++) {
        const __half* __restrict__ hin = g_h[t & 1];
        __half* __restrict__ hout      = g_h[(t + 1) & 1];

        if (t > 0) {
            if (tid == 0) while (ld_acquire_gpu(&g_flag[t - 1]) != SCAN_BLOCKS) {}
            __syncthreads();
        }

        const __half* hsrc = hin + (size_t)(mhalf * 64) * H_;

        // preload pair 0 (chunks 0,1 -> slots 0,1): 2048 16B lines, 4/thread
#pragma unroll
        for (int i = 0; i < 4; i++) {
            int cid = tid + i * SCAN_THREADS;
            int half = cid >> 10, q = cid & 1023;
            int r = q >> 4, ch = q & 15;
            cp_async16(hs_base + (uint32_t)(((half * CHK) + r * HS_LD + ch * 8) * 2),
                       hsrc + (size_t)r * H_ + half * 128 + ch * 8);
        }
        asm volatile("cp.async.commit_group;\n");

        float acc[4][4];
#pragma unroll
        for (int g = 0; g < 4; g++)
#pragma unroll
            for (int e = 0; e < 4; e++) acc[g][e] = 0.f;

#pragma unroll 1
        for (int p = 0; p < 4; p++) {
            asm volatile("cp.async.wait_group 0;\n");
            __syncthreads();
            if (p < 3) {
                const int sb = 2 * ((p + 1) & 1);
#pragma unroll
                for (int i = 0; i < 4; i++) {
                    int cid = tid + i * SCAN_THREADS;
                    int half = cid >> 10, q = cid & 1023;
                    int r = q >> 4, ch = q & 15;
                    cp_async16(hs_base + (uint32_t)((((sb + half) * CHK) + r * HS_LD + ch * 8) * 2),
                               hsrc + (size_t)r * H_ + ((p + 1) * 2 + half) * 128 + ch * 8);
                }
                asm volatile("cp.async.commit_group;\n");
            }

            // compute chunk c = 2p+kg from slot 2*(p&1)+kg
            const int c    = 2 * p + kg;
            const int slot = 2 * (p & 1) + kg;
            uint32_t aA = hs_base + (uint32_t)(slot * CHK * 2) + a_lane_off;
            uint32_t aB0 = b_lane0 + (uint32_t)(c * 256);
            uint32_t aB1 = b_lane1 + (uint32_t)(c * 256);
#pragma unroll
            for (int ks = 0; ks < 8; ks++) {
                uint32_t a[4], b01[4], b23[4];
                ldsm_x4(a,   aA  + ks * 32);
                ldsm_x4(b01, aB0 + ks * 32);
                ldsm_x4(b23, aB1 + ks * 32);
                mma16816(acc[0], a, b01[0], b01[1]);
                mma16816(acc[1], a, b01[2], b01[3]);
                mma16816(acc[2], a, b23[0], b23[1]);
                mma16816(acc[3], a, b23[2], b23[3]);
            }
        }

        // ---- merge k-halves: kg1 -> SMEM (stride 20 floats, conflict-free) ----
        float* red = (float*)hs;
        const int rb = (ww * 32 + lane) * 20;
        if (kg == 1) {
#pragma unroll
            for (int g = 0; g < 4; g++)
                *(float4*)&red[rb + g * 4] = make_float4(acc[g][0], acc[g][1], acc[g][2], acc[g][3]);
        }
        __syncthreads();

        if (kg == 0) {
#pragma unroll
            for (int g = 0; g < 4; g++) {
                float4 v = *(const float4*)&red[rb + g * 4];
                acc[g][0] += v.x; acc[g][1] += v.y; acc[g][2] += v.z; acc[g][3] += v.w;
            }
            // ---- epilogue: gates + cell update + writes ----
#pragma unroll
            for (int rr = 0; rr < 2; rr++) {
                const int b_row = mhalf * 64 + my_r + rr * 8;
                const size_t gxb = ((size_t)t * B_ + b_row) * NG + my_j;
                float2 ff = __half22float2(*(const __half2*)&g_gx[gxb + 0 * H_]);
                float2 fi = __half22float2(*(const __half2*)&g_gx[gxb + 1 * H_]);
                float2 fc = __half22float2(*(const __half2*)&g_gx[gxb + 2 * H_]);
                float2 fo = __half22float2(*(const __half2*)&g_gx[gxb + 3 * H_]);

                float hres[2];
#pragma unroll
                for (int cc = 0; cc < 2; cc++) {
                    const int ai = rr * 2 + cc;
                    float pf = acc[0][ai] + (cc ? ff.y : ff.x);
                    float pi = acc[1][ai] + (cc ? fi.y : fi.x);
                    float pc = acc[2][ai] + (cc ? fc.y : fc.x);
                    float po = acc[3][ai] + (cc ? fo.y : fo.x);
                    float f = sigm(pf), ii = sigm(pi), ct = tanh_fast(pc), o = sigm(po);
                    float cn = f * cst[ai] + ii * ct;
                    cst[ai] = cn;
                    hres[cc] = o * tanh_fast(cn);
                }
                *(float2*)&out[((size_t)t * B_ + b_row) * H_ + my_j] = make_float2(hres[0], hres[1]);
                *(__half2*)&hout[(size_t)b_row * H_ + my_j] = __floats2half2_rn(hres[0], hres[1]);
            }
        }

        __threadfence();
        __syncthreads();
        if (tid == 0) atomicAdd(&g_flag[t], 1);
    }
}

// ---------------- launch ----------------------------------------------------
extern "C" void kernel_launch(void* const* d_in, const int* in_sizes, int n_in,
                              void* d_out, int out_size) {
    const float* x  = (const float*)d_in[0];
    const float* Wf = (const float*)d_in[1];
    const float* bf = (const float*)d_in[2];
    const float* Wi = (const float*)d_in[3];
    const float* bi = (const float*)d_in[4];
    const float* Wc = (const float*)d_in[5];
    const float* bc = (const float*)d_in[6];
    const float* Wo = (const float*)d_in[7];
    const float* bo = (const float*)d_in[8];
    float* out = (float*)d_out;

    cudaFuncSetAttribute(k_scan, cudaFuncAttributeMaxDynamicSharedMemorySize, SCAN_SMEM);

    {
        size_t total = (size_t)NG * KZ;
        k_prep_weights<<<(int)((total + 255) / 256), 256>>>(Wf, Wi, Wc, Wo);
    }
    {
        size_t total = (size_t)T_ * B_ * I_;
        k_convert_x<<<(int)((total + 255) / 256), 256>>>(x);
    }
    k_gx<<<dim3(NG / 128, (T_ * B_) / 128), 256>>>(bf, bi, bc, bo);

    k_scan<<<SCAN_BLOCKS, SCAN_THREADS, SCAN_SMEM>>>(out);
}

// round 7
// speedup vs baseline: 1.0342x; 1.0030x over previous
#include <cuda_runtime.h>
#include <cuda_fp16.h>
#include <cstdint>

#define T_  512
#define B_  128
#define I_  512
#define H_  1024
#define NG  4096
#define KZ  1536
#define SCAN_BLOCKS  128
#define SCAN_THREADS 512

__device__ __half g_xh[(size_t)T_ * B_ * I_];
__device__ __half g_gx[(size_t)T_ * B_ * NG];
__device__ __half g_Wh[(size_t)NG * H_];
__device__ __half g_Wx[(size_t)NG * I_];
// h ping-pong, k-chunked + padded rows: [buf][kchunk][row][136]
__device__ __align__(1024) __half g_hk[2][8][128][136];
__device__ int g_done[SCAN_BLOCKS];

__device__ __forceinline__ float sigm(float x) { return 1.0f / (1.0f + __expf(-x)); }
__device__ __forceinline__ float tanh_fast(float x) {
    float e = __expf(-2.0f * fabsf(x));
    return copysignf((1.0f - e) / (1.0f + e), x);
}
__device__ __forceinline__ void mma16816(float* d, const uint32_t* a, uint32_t b0, uint32_t b1) {
    asm volatile(
        "mma.sync.aligned.m16n8k16.row.col.f32.f16.f16.f32 "
        "{%0,%1,%2,%3}, {%4,%5,%6,%7}, {%8,%9}, {%0,%1,%2,%3};\n"
        : "+f"(d[0]), "+f"(d[1]), "+f"(d[2]), "+f"(d[3])
        : "r"(a[0]), "r"(a[1]), "r"(a[2]), "r"(a[3]), "r"(b0), "r"(b1));
}
__device__ __forceinline__ void ldsm_x4(uint32_t* r, uint32_t addr) {
    asm volatile("ldmatrix.sync.aligned.m8n8.x4.shared.b16 {%0,%1,%2,%3}, [%4];"
                 : "=r"(r[0]), "=r"(r[1]), "=r"(r[2]), "=r"(r[3]) : "r"(addr));
}
__device__ __forceinline__ int ld_acquire_gpu(const int* p) {
    int v; asm volatile("ld.acquire.gpu.b32 %0, [%1];\n" : "=r"(v) : "l"(p) : "memory"); return v;
}
__device__ __forceinline__ void st_release_gpu(int* p, int v) {
    asm volatile("st.release.gpu.global.b32 [%0], %1;\n" :: "l"(p), "r"(v) : "memory");
}
__device__ __forceinline__ uint32_t smem_u32(const void* p) {
    uint32_t a; asm("{ .reg .u64 t; cvta.to.shared.u64 t, %1; cvt.u32.u64 %0, t; }" : "=r"(a) : "l"(p)); return a;
}
__device__ __forceinline__ void mbar_init(uint32_t m, uint32_t c) {
    asm volatile("mbarrier.init.shared.b64 [%0], %1;" :: "r"(m), "r"(c) : "memory");
}
__device__ __forceinline__ void mbar_expect_tx(uint32_t m, uint32_t bytes) {
    asm volatile("mbarrier.arrive.expect_tx.shared.b64 _, [%0], %1;" :: "r"(m), "r"(bytes) : "memory");
}
__device__ __forceinline__ void mbar_wait(uint32_t m, uint32_t par) {
    asm volatile(
        "{\n\t.reg .pred P1;\n\t"
        "WL_%=:\n\t"
        "mbarrier.try_wait.parity.shared.b64 P1, [%0], %1;\n\t"
        "@P1 bra.uni WD_%=;\n\tbra.uni WL_%=;\n\tWD_%=:\n\t}"
        :: "r"(m), "r"(par) : "memory");
}
__device__ __forceinline__ void bulk_g2s(uint32_t dst, const void* src, uint32_t bytes, uint32_t mbar) {
    asm volatile("cp.async.bulk.shared::cluster.global.mbarrier::complete_tx::bytes [%0], [%1], %2, [%3];"
                 :: "r"(dst), "l"(src), "r"(bytes), "r"(mbar) : "memory");
}
__device__ __forceinline__ void fence_pa() { asm volatile("fence.proxy.async.shared::cta;" ::: "memory"); }

// ---------------- prep ----------------------------------------------------
__global__ void k_prep_weights(const float* __restrict__ Wf, const float* __restrict__ Wi,
                               const float* __restrict__ Wc, const float* __restrict__ Wo) {
    size_t idx = (size_t)blockIdx.x * blockDim.x + threadIdx.x;
    if (idx < (size_t)NG * KZ) {
        int n = (int)(idx / KZ), k = (int)(idx % KZ);
        int g = n >> 10, j = n & 1023;
        const float* W = (g == 0) ? Wf : (g == 1) ? Wi : (g == 2) ? Wc : Wo;
        float v = W[(size_t)j * KZ + k];
        if (k < H_) g_Wh[(size_t)n * H_ + k]        = __float2half(v);
        else        g_Wx[(size_t)n * I_ + (k - H_)] = __float2half(v);
    }
    if (idx < (size_t)2 * 8 * 128 * 136) ((__half*)g_hk)[idx] = __float2half(0.0f);
    if (idx < SCAN_BLOCKS) g_done[idx] = 0;
}

__global__ void k_convert_x(const float* __restrict__ x) {
    size_t idx = (size_t)blockIdx.x * blockDim.x + threadIdx.x;
    if (idx < (size_t)T_ * B_ * I_) g_xh[idx] = __float2half(x[idx]);
}

// ---------------- gx GEMM (unchanged, passing) -----------------------------
__global__ __launch_bounds__(256) void k_gx(const float* __restrict__ bf, const float* __restrict__ bi,
                                            const float* __restrict__ bc, const float* __restrict__ bo) {
    __shared__ __half As[128][40];
    __shared__ __half Bs[128][40];
    const int m0 = blockIdx.y * 128, n0 = blockIdx.x * 128;
    const int tid = threadIdx.x, w = tid >> 5, lane = tid & 31;
    const int gid = lane >> 2, t4 = lane & 3, wm = w >> 1, wn = w & 1;

    float acc[2][8][4];
#pragma unroll
    for (int mt = 0; mt < 2; mt++)
#pragma unroll
        for (int nt = 0; nt < 8; nt++)
#pragma unroll
            for (int e = 0; e < 4; e++) acc[mt][nt][e] = 0.0f;

    for (int kb = 0; kb < I_; kb += 32) {
#pragma unroll
        for (int i = 0; i < 2; i++) {
            int cid = tid + i * 256, r = cid >> 2, ch = cid & 3;
            *(uint4*)&As[r][ch * 8] = *(const uint4*)&g_xh[(size_t)(m0 + r) * I_ + kb + ch * 8];
            *(uint4*)&Bs[r][ch * 8] = *(const uint4*)&g_Wx[(size_t)(n0 + r) * I_ + kb + ch * 8];
        }
        __syncthreads();
#pragma unroll
        for (int ks = 0; ks < 2; ks++) {
            const int ko = ks * 16;
            uint32_t a[2][4], b[8][2];
#pragma unroll
            for (int mt = 0; mt < 2; mt++) {
                int r = wm * 32 + mt * 16 + gid;
                a[mt][0] = *(const uint32_t*)&As[r][ko + t4 * 2];
                a[mt][1] = *(const uint32_t*)&As[r + 8][ko + t4 * 2];
                a[mt][2] = *(const uint32_t*)&As[r][ko + t4 * 2 + 8];
                a[mt][3] = *(const uint32_t*)&As[r + 8][ko + t4 * 2 + 8];
            }
#pragma unroll
            for (int nt = 0; nt < 8; nt++) {
                int c = wn * 64 + nt * 8 + gid;
                b[nt][0] = *(const uint32_t*)&Bs[c][ko + t4 * 2];
                b[nt][1] = *(const uint32_t*)&Bs[c][ko + t4 * 2 + 8];
            }
#pragma unroll
            for (int mt = 0; mt < 2; mt++)
#pragma unroll
                for (int nt = 0; nt < 8; nt++)
                    mma16816(acc[mt][nt], a[mt], b[nt][0], b[nt][1]);
        }
        __syncthreads();
    }
#pragma unroll
    for (int nt = 0; nt < 8; nt++) {
        int n = n0 + wn * 64 + nt * 8 + t4 * 2;
        int g = n >> 10, j = n & 1023;
        const float* bias = (g == 0) ? bf : (g == 1) ? bi : (g == 2) ? bc : bo;
        float b0 = bias[j], b1 = bias[j + 1];
#pragma unroll
        for (int mt = 0; mt < 2; mt++) {
            int m = m0 + wm * 32 + mt * 16 + gid;
            *(__half2*)&g_gx[(size_t)m * NG + n]       = __floats2half2_rn(acc[mt][nt][0] + b0, acc[mt][nt][1] + b1);
            *(__half2*)&g_gx[(size_t)(m + 8) * NG + n] = __floats2half2_rn(acc[mt][nt][2] + b0, acc[mt][nt][3] + b1);
        }
    }
}

// ---------------- persistent LSTM scan: bulk-copy h + HMMA ------------------
// 128 blocks x 512 thr. Block (mhalf,jb): rows mhalf*64(+64) x 16 j x 4 gates.
// h streamed as 8 bulk copies (17408B each, one instr) into a 4-buffer ring.
// Warps kg=0 compute even k-chunks, kg=1 odd; SMEM reduce merges; fused epilogue.
#define HS_LD 136
#define CHKB  (64 * HS_LD * 2)       // 17408 bytes per chunk
#define WS_LD 1032
#define WS_HALFS (64 * WS_LD)
#define WS_BYTES (WS_HALFS * 2)      // 132096
#define HB_OFF   WS_BYTES
#define SCAN_SMEM (WS_BYTES + 4 * CHKB)

__global__ __launch_bounds__(SCAN_THREADS, 1) void k_scan(float* __restrict__ out) {
    extern __shared__ __half sm[];
    __half* ws = sm;                 // [64][WS_LD], row = g*16 + jl
    __half* hs = sm + WS_HALFS;      // 4 ring buffers [64][HS_LD]
    __shared__ __align__(8) uint64_t s_mbar[4];

    const int tid  = threadIdx.x;
    const int w    = tid >> 5;
    const int lane = tid & 31;
    const int kg   = w >> 3;         // 0/1: even/odd k-chunks
    const int ww   = w & 7;
    const int wm   = ww >> 1;        // 0..3 m-tile
    const int wn   = ww & 1;         // 0..1 j-half
    const int gid  = lane >> 2;
    const int t4   = lane & 3;

    const int bid   = blockIdx.x;
    const int mhalf = bid & 1;
    const int jb    = bid >> 1;
    const int j0    = jb * 16;

    // ---- Wh slice once ----
#pragma unroll 4
    for (int i = 0; i < 16; i++) {
        int cid = tid + i * SCAN_THREADS;
        int r = cid >> 7, ch = cid & 127;
        int g = r >> 4, jl = r & 15;
        *(uint4*)&ws[r * WS_LD + ch * 8] =
            *(const uint4*)&g_Wh[(size_t)(g * H_ + j0 + jl) * H_ + ch * 8];
    }

    const uint32_t hs_base = smem_u32(hs);
    const uint32_t ws_base = smem_u32(ws);
    uint32_t mb[4];
#pragma unroll
    for (int i = 0; i < 4; i++) mb[i] = smem_u32(&s_mbar[i]);
    if (tid == 0) {
#pragma unroll
        for (int i = 0; i < 4; i++) mbar_init(mb[i], 1);
        fence_pa();
    }
    __syncthreads();

    // ldmatrix lane addresses (bytes)
    const int a_row = wm * 16 + ((lane >> 3) & 1) * 8 + (lane & 7);
    const uint32_t a_lane_off = (uint32_t)((a_row * HS_LD + (lane >> 4) * 8) * 2);
    const uint32_t b_lane0 = ws_base + (uint32_t)(((((lane >> 4) + 0) * 16 + wn * 8 + (lane & 7)) * WS_LD
                                                   + ((lane >> 3) & 1) * 8) * 2);
    const uint32_t b_lane1 = ws_base + (uint32_t)(((((lane >> 4) + 2) * 16 + wn * 8 + (lane & 7)) * WS_LD
                                                   + ((lane >> 3) & 1) * 8) * 2);

    const int my_r = wm * 16 + gid;
    const int my_j = j0 + wn * 8 + t4 * 2;

    float cst[4] = {0.f, 0.f, 0.f, 0.f};    // kg0 warps only
    int ph[4] = {0, 0, 0, 0};                // per-buffer mbar parity

    for (int t = 0; t < T_; t++) {
        const int hbuf = t & 1;

        // gx prefetch: independent of h, flies during the flag wait
        uint4 gq[8];
        if (tid < 256) {
            const __half* gp = &g_gx[((size_t)t * B_ + mhalf * 64 + my_r) * NG + my_j];
            // rows my_r and my_r+8, per gate: 2 half2 each (loaded as scalars below in epilogue form)
            // load as 8x16B straddling gates for rows rr=0,1
#pragma unroll
            for (int g = 0; g < 4; g++) {
                gq[g]     = __ldg((const uint4*)((const char*)gp + (size_t)g * H_ * 2 - (my_j & 7) * 2));
                gq[4 + g] = __ldg((const uint4*)((const char*)(gp + 8 * NG) + (size_t)g * H_ * 2 - (my_j & 7) * 2));
            }
        }

        if (t > 0) {
            if (tid < 64) {
                const int* p = &g_done[mhalf + 2 * tid];
                while (ld_acquire_gpu(p) < t) {}
            }
            __syncthreads();
        }

        // issue chunks 0..3
        if (tid == 0) {
#pragma unroll
            for (int c = 0; c < 4; c++) {
                mbar_expect_tx(mb[c], CHKB);
                bulk_g2s(hs_base + (uint32_t)(c * CHKB), &g_hk[hbuf][c][mhalf * 64][0], CHKB, mb[c]);
            }
        }

        float acc[4][4];
#pragma unroll
        for (int g = 0; g < 4; g++)
#pragma unroll
            for (int e = 0; e < 4; e++) acc[g][e] = 0.f;

#pragma unroll 1
        for (int c = 0; c < 8; c++) {
            const int b = c & 3;
            mbar_wait(mb[b], (uint32_t)ph[b]);
            ph[b] ^= 1;

            if ((c & 1) == kg) {
                uint32_t aA  = hs_base + (uint32_t)(b * CHKB) + a_lane_off;
                uint32_t aB0 = b_lane0 + (uint32_t)(c * 256);
                uint32_t aB1 = b_lane1 + (uint32_t)(c * 256);
#pragma unroll
                for (int ks = 0; ks < 8; ks++) {
                    uint32_t a[4], b01[4], b23[4];
                    ldsm_x4(a,   aA  + ks * 32);
                    ldsm_x4(b01, aB0 + ks * 32);
                    ldsm_x4(b23, aB1 + ks * 32);
                    mma16816(acc[0], a, b01[0], b01[1]);
                    mma16816(acc[1], a, b01[2], b01[3]);
                    mma16816(acc[2], a, b23[0], b23[1]);
                    mma16816(acc[3], a, b23[2], b23[3]);
                }
            }
            if (c < 4) {
                __syncthreads();
                if (tid == 0) {
                    mbar_expect_tx(mb[b], CHKB);
                    bulk_g2s(hs_base + (uint32_t)(b * CHKB), &g_hk[hbuf][c + 4][mhalf * 64][0], CHKB, mb[b]);
                }
            }
        }

        // ---- merge k-halves via SMEM (stride 20 floats) ----
        float* red = (float*)hs;
        const int rb = (ww * 32 + lane) * 20;
        if (kg == 1) {
#pragma unroll
            for (int g = 0; g < 4; g++)
                *(float4*)&red[rb + g * 4] = make_float4(acc[g][0], acc[g][1], acc[g][2], acc[g][3]);
        }
        __syncthreads();

        if (kg == 0) {
#pragma unroll
            for (int g = 0; g < 4; g++) {
                float4 v = *(const float4*)&red[rb + g * 4];
                acc[g][0] += v.x; acc[g][1] += v.y; acc[g][2] += v.z; acc[g][3] += v.w;
            }
            const int jc  = my_j >> 7;          // k-chunk of my j
            const int jcc = my_j & 127;
            const __half* gxh = (const __half*)gq;   // [rr0: g0..g3][rr1: g0..g3], 8 halfs each, idx (my_j&7)..
            const int lo = my_j & 7;
#pragma unroll
            for (int rr = 0; rr < 2; rr++) {
                const int b_row = mhalf * 64 + my_r + rr * 8;
                float hres[2];
#pragma unroll
                for (int cc = 0; cc < 2; cc++) {
                    const int ai = rr * 2 + cc;
                    float pf = acc[0][ai] + __half2float(gxh[(rr * 4 + 0) * 8 + lo + cc]);
                    float pi = acc[1][ai] + __half2float(gxh[(rr * 4 + 1) * 8 + lo + cc]);
                    float pc = acc[2][ai] + __half2float(gxh[(rr * 4 + 2) * 8 + lo + cc]);
                    float po = acc[3][ai] + __half2float(gxh[(rr * 4 + 3) * 8 + lo + cc]);
                    float f = sigm(pf), ii = sigm(pi), ct = tanh_fast(pc), o = sigm(po);
                    float cn = f * cst[ai] + ii * ct;
                    cst[ai] = cn;
                    hres[cc] = o * tanh_fast(cn);
                }
                *(float2*)&out[((size_t)t * B_ + b_row) * H_ + my_j] = make_float2(hres[0], hres[1]);
                *(__half2*)&g_hk[hbuf ^ 1][jc][b_row][jcc] = __floats2half2_rn(hres[0], hres[1]);
            }
        }

        __syncthreads();
        __threadfence();
        if (tid == 0) st_release_gpu(&g_done[bid], t + 1);
    }
}

// ---------------- launch ----------------------------------------------------
extern "C" void kernel_launch(void* const* d_in, const int* in_sizes, int n_in,
                              void* d_out, int out_size) {
    const float* x  = (const float*)d_in[0];
    const float* Wf = (const float*)d_in[1];
    const float* bf = (const float*)d_in[2];
    const float* Wi = (const float*)d_in[3];
    const float* bi = (const float*)d_in[4];
    const float* Wc = (const float*)d_in[5];
    const float* bc = (const float*)d_in[6];
    const float* Wo = (const float*)d_in[7];
    const float* bo = (const float*)d_in[8];
    float* out = (float*)d_out;

    cudaFuncSetAttribute(k_scan, cudaFuncAttributeMaxDynamicSharedMemorySize, SCAN_SMEM);

    {
        size_t total = (size_t)NG * KZ;
        k_prep_weights<<<(int)((total + 255) / 256), 256>>>(Wf, Wi, Wc, Wo);
    }
    {
        size_t total = (size_t)T_ * B_ * I_;
        k_convert_x<<<(int)((total + 255) / 256), 256>>>(x);
    }
    k_gx<<<dim3(NG / 128, (T_ * B_) / 128), 256>>>(bf, bi, bc, bo);

    k_scan<<<SCAN_BLOCKS, SCAN_THREADS, SCAN_SMEM>>>(out);
}